// round 11
// baseline (speedup 1.0000x reference)
#include <cuda_runtime.h>
#include <math.h>

#define Bn 4
#define Cn 16
#define Nn 384
#define NP (Nn*Nn)

#define R1   8           // rows per block (k1/k2)
#define R3   4           // rows per block (k3a)
#define EXRS 408         // exchange row stride (24*17)
#define EX2RS 401        // second-exchange row stride (16*25 + pad)
#define SXS  9           // transpose-store stride (R1+1)
#define BUF1 3456        // max(8*408, 384*9, 8*401)
#define BUF3 1632        // 4*408 for k3a

// Static device scratch (allocation-free)
__device__ float2 g_T1[(size_t)Bn*Cn*NP];   // [b,c,kw,h]
__device__ float2 g_T2[(size_t)Bn*Cn*NP];   // [b,c,h,kw]
__device__ float2 g_csm2[(size_t)Bn*Cn*NP]; // interleaved csm [b,c,h,w]
__device__ float2 g_x[Bn*NP];
__device__ float2 g_y[Bn*NP];
__device__ float2 g_grad[Bn*NP];
__device__ float4 g_mb[Bn*NP];              // {m, m*br, m*bi, 0}, [b,kw,kh]
__device__ float2 g_tw[Nn];                 // exp(-2*pi*i*k/384)

// NOTE: cW24 indices are always compile-time (uniform LDC broadcast — fine).
__constant__ float2 cW24[15] = {
 {1.f,0.f},{0.9659258263f,-0.2588190451f},{0.8660254038f,-0.5f},
 {0.7071067812f,-0.7071067812f},{0.5f,-0.8660254038f},{0.2588190451f,-0.9659258263f},
 {0.f,-1.f},{-0.2588190451f,-0.9659258263f},{-0.5f,-0.8660254038f},
 {-0.7071067812f,-0.7071067812f},{-0.8660254038f,-0.5f},{-0.9659258263f,-0.2588190451f},
 {-1.f,0.f},{-0.9659258263f,0.2588190451f},{-0.8660254038f,0.5f}};

__device__ __forceinline__ float2 cmul(float2 a, float2 b){
    return make_float2(fmaf(a.x,b.x,-a.y*b.y), fmaf(a.x,b.y, a.y*b.x));
}
__device__ __forceinline__ float2 cadd(float2 a, float2 b){ return make_float2(a.x+b.x, a.y+b.y); }
__device__ __forceinline__ float2 csub(float2 a, float2 b){ return make_float2(a.x-b.x, a.y-b.y); }

template<bool INV>
__device__ __forceinline__ void fft3(float2& a, float2& b, float2& c){
    const float s = INV ? 0.8660254037844386f : -0.8660254037844386f;
    float2 t = cadd(b,c);
    float2 d = csub(b,c);
    float2 m = make_float2(a.x - 0.5f*t.x, a.y - 0.5f*t.y);
    float2 e = make_float2(-s*d.y, s*d.x);
    a = cadd(a,t);
    b = make_float2(m.x + e.x, m.y + e.y);
    c = make_float2(m.x - e.x, m.y - e.y);
}

template<bool INV>
__device__ __forceinline__ void fft4(float2 v[4]){
    float2 t0=cadd(v[0],v[2]), t1=csub(v[0],v[2]);
    float2 t2=cadd(v[1],v[3]), t3=csub(v[1],v[3]);
    float2 j = INV ? make_float2(-t3.y, t3.x) : make_float2(t3.y, -t3.x);
    v[0]=cadd(t0,t2); v[2]=csub(t0,t2);
    v[1]=cadd(t1,j);  v[3]=csub(t1,j);
}

template<bool INV>
__device__ __forceinline__ void fft8(float2 v[8]){
    float2 e[4]={v[0],v[2],v[4],v[6]}, o[4]={v[1],v[3],v[5],v[7]};
    fft4<INV>(e); fft4<INV>(o);
    const float r=0.70710678118654752f;
    float2 w1 = INV? make_float2(r,r)  : make_float2(r,-r);
    float2 w2 = INV? make_float2(0.f,1.f): make_float2(0.f,-1.f);
    float2 w3 = INV? make_float2(-r,r) : make_float2(-r,-r);
    float2 t;
    t=o[0];          v[0]=cadd(e[0],t); v[4]=csub(e[0],t);
    t=cmul(o[1],w1); v[1]=cadd(e[1],t); v[5]=csub(e[1],t);
    t=cmul(o[2],w2); v[2]=cadd(e[2],t); v[6]=csub(e[2],t);
    t=cmul(o[3],w3); v[3]=cadd(e[3],t); v[7]=csub(e[3],t);
}

// fft16 with twiddles pulled from the smem tw table: W16^j = W384^(24j).
// Avoids divergent constant-cache loads (k2 is thread-dependent).
template<bool INV>
__device__ __forceinline__ void fft16(float2 v[16], const float2* __restrict__ tw){
    #pragma unroll
    for (int n1=0;n1<4;n1++){
        float2 a[4]={v[n1],v[n1+4],v[n1+8],v[n1+12]};
        fft4<INV>(a);
        v[n1]=a[0]; v[n1+4]=a[1]; v[n1+8]=a[2]; v[n1+12]=a[3];
    }
    float2 out[16];
    #pragma unroll
    for (int k2=0;k2<4;k2++){
        float2 a[4];
        #pragma unroll
        for (int n1=0;n1<4;n1++){
            float2 g = v[n1+4*k2];
            if (k2==0 || n1==0) a[n1]=g;
            else {
                float2 w = tw[24*n1*k2];
                if(INV) w.y=-w.y;
                a[n1]=cmul(g,w);
            }
        }
        fft4<INV>(a);
        #pragma unroll
        for (int k1=0;k1<4;k1++) out[k2+4*k1]=a[k1];
    }
    #pragma unroll
    for (int i=0;i<16;i++) v[i]=out[i];
}

// Natural-in / natural-out 24-pt FFT in registers (all twiddles compile-time)
template<bool INV>
__device__ __forceinline__ void fft24(float2 v[24], float2 out[24]){
    #pragma unroll
    for (int m1=0;m1<8;m1++) fft3<INV>(v[m1], v[m1+8], v[m1+16]);
    #pragma unroll
    for (int q2=0;q2<3;q2++){
        float2 a[8];
        #pragma unroll
        for (int m1=0;m1<8;m1++){
            float2 g = v[m1+8*q2];
            if (q2==0 || m1==0) a[m1]=g;
            else { float2 w=cW24[m1*q2]; if(INV) w.y=-w.y; a[m1]=cmul(g,w); }
        }
        fft8<INV>(a);
        #pragma unroll
        for (int q1=0;q1<8;q1++) out[q2+3*q1]=a[q1];
    }
}

// 24-pt FFT in registers + W384^{n1*k} twiddle + scatter to exchange buffer
template<bool INV>
__device__ __forceinline__ void phaseA(float2 v[24], float2* exrow, int n1,
                                       const float2* __restrict__ tw)
{
    float2 o[24];
    fft24<INV>(v, o);
    #pragma unroll
    for (int k=0;k<24;k++){
        float2 w = tw[n1*k]; if(INV) w.y=-w.y;
        exrow[k*17 + n1] = cmul(o[k], w);
    }
}

// ---------------------------------------------------------------------------
__global__ void k0_tw()
{
    int i = threadIdx.x;
    if (i < Nn) {
        double th = -2.0 * 3.14159265358979323846 * (double)i / (double)Nn;
        g_tw[i] = make_float2((float)cos(th), (float)sin(th));
    }
}

// zero state + build mask/b pack (merged)
__global__ void k0_init(const float* __restrict__ x0, const int* __restrict__ mask)
{
    for (int i = blockIdx.x*blockDim.x + threadIdx.x; i < Bn*NP; i += gridDim.x*blockDim.x) {
        g_x[i] = make_float2(0.f,0.f);
        g_y[i] = make_float2(0.f,0.f);
        g_grad[i] = make_float2(0.f,0.f);
        int b   = i / NP;
        int rem = i - b*NP;
        int w   = rem / Nn;
        int h   = rem - w*Nn;
        int hi  = h*Nn + w;
        float m = (float)mask[b*NP + hi];
        float xr = x0[(size_t)(2*b  )*NP + hi];
        float xi = x0[(size_t)(2*b+1)*NP + hi];
        g_mb[i] = make_float4(m, m*xr, m*xi, 0.f);
    }
}

// interleave csm once: g_csm2[(b*Cn+c)*NP + p] = {re, im}
__global__ void k0_csm(const float* __restrict__ csm)
{
    for (size_t i = (size_t)blockIdx.x*blockDim.x + threadIdx.x;
         i < (size_t)Bn*Cn*NP; i += (size_t)gridDim.x*blockDim.x) {
        size_t p  = i % NP;
        size_t bc = i / NP;
        size_t c  = bc % Cn;
        size_t b  = bc / Cn;
        float re = csm[((b*2+0)*Cn + c)*NP + p];
        float im = csm[((b*2+1)*Cn + c)*NP + p];
        g_csm2[i] = make_float2(re, im);
    }
}

// ---------------------------------------------------------------------------
// K1: fwd FFT over w of coil*y; transposed write to g_T1[b,c,kw,h]
// ---------------------------------------------------------------------------
__global__ void __launch_bounds__(192,5) k1_fwd_rows()
{
    __shared__ float2 tw[Nn];
    __shared__ float2 buf[BUF1];
    const int tid = threadIdx.x;
    for (int i=tid;i<Nn;i+=192) tw[i]=g_tw[i];
    const int blk = blockIdx.x;
    const int h0 = (blk % 48)*R1;
    const int c  = (blk / 48) % Cn;
    const int b  =  blk / (48*Cn);
    __syncthreads();

    if (tid < 16*R1) {
        int row=tid>>4, n1=tid&15;
        int h=h0+row;
        const float2* cp = g_csm2 + ((size_t)(b*Cn+c))*NP + (size_t)h*Nn;
        const float2* yp = g_y + (size_t)b*NP + (size_t)h*Nn;
        float2 v[24];
        #pragma unroll
        for (int n2=0;n2<24;n2++){
            int n = n1+16*n2;
            v[n2] = cmul(cp[n], yp[n]);
        }
        phaseA<false>(v, buf + row*EXRS, n1, tw);
    }
    __syncthreads();
    {
        int row=tid/24, k2=tid-row*24;
        float2 hh[16];
        #pragma unroll
        for (int n1=0;n1<16;n1++) hh[n1]=buf[row*EXRS + k2*17 + n1];
        fft16<false>(hh, tw);
        __syncthreads();
        #pragma unroll
        for (int k1=0;k1<16;k1++) buf[(k2+24*k1)*SXS + row] = hh[k1];
    }
    __syncthreads();
    // vectorized writeout: 4 float4 per k (rows h0..h0+7 are consecutive)
    float4* T1v = (float4*)(g_T1 + (size_t)(b*Cn+c)*NP);
    for (int j=tid;j<Nn*4;j+=192){
        int k=j>>2, q=j&3;
        float2 a0 = buf[k*SXS + 2*q];
        float2 a1 = buf[k*SXS + 2*q + 1];
        T1v[((size_t)k*Nn + h0)/2 + q] = make_float4(a0.x, a0.y, a1.x, a1.y);
    }
}

// ---------------------------------------------------------------------------
// K2: fwd FFT over h, mask & subtract, reverse-network inv FFT over h.
// Reads g_T1[b,c,kw,h]; writes g_T2[b,c,h,kw] (scaled 1/384).
// ---------------------------------------------------------------------------
__global__ void __launch_bounds__(192,5) k2_cols()
{
    __shared__ float2 tw[Nn];
    __shared__ float2 buf[BUF1];
    const int tid = threadIdx.x;
    for (int i=tid;i<Nn;i+=192) tw[i]=g_tw[i];
    const int blk = blockIdx.x;
    const int w0 = (blk % 48)*R1;
    const int c  = (blk / 48) % Cn;
    const int b  =  blk / (48*Cn);
    __syncthreads();

    // phase 1: load + fwd phaseA (128 threads)
    const float2* T1 = g_T1 + (size_t)(b*Cn+c)*NP;
    if (tid < 16*R1){
        int rowA=tid>>4, n1=tid&15;
        const float2* src = T1 + (size_t)(w0+rowA)*Nn;
        float2 v[24];
        #pragma unroll
        for (int n2=0;n2<24;n2++) v[n2]=src[n1+16*n2];
        phaseA<false>(v, buf + rowA*EXRS, n1, tw);
    }
    __syncthreads();

    // phase 2: fft16 fwd, mask, fft16 inv (registers), conj twiddle
    const int row=tid/24, k2=tid-row*24;
    float2 hh[16];
    #pragma unroll
    for (int n1=0;n1<16;n1++) hh[n1]=buf[row*EXRS + k2*17 + n1];
    fft16<false>(hh, tw);
    {
        int w = w0+row;
        const float4* mb = g_mb + (size_t)b*NP + (size_t)w*Nn;
        #pragma unroll
        for (int k1=0;k1<16;k1++){
            int k = k2+24*k1;
            float4 q = mb[k];
            hh[k1] = make_float2(q.x*hh[k1].x - q.y, q.x*hh[k1].y - q.z);
        }
    }
    fft16<true>(hh, tw);      // inner inverse over k1; hh now indexed by n1
    __syncthreads();
    #pragma unroll
    for (int n1=0;n1<16;n1++){
        float2 wv = tw[n1*k2]; wv.y = -wv.y;     // W384^{+n1*k2}
        buf[row*EX2RS + n1*25 + k2] = cmul(hh[n1], wv);
    }
    __syncthreads();

    // phase 3: fft24 inverse over k2 (128 threads), scale, transpose store
    if (tid < 16*R1){
        int rowA=tid>>4, n1=tid&15;
        float2 u[24], xr[24];
        #pragma unroll
        for (int j2=0;j2<24;j2++) u[j2]=buf[rowA*EX2RS + n1*25 + j2];
        fft24<true>(u, xr);
        __syncthreads();
        const float sc = 1.0f/(float)Nn;
        #pragma unroll
        for (int n2=0;n2<24;n2++)
            buf[(n1+16*n2)*SXS + rowA] = make_float2(xr[n2].x*sc, xr[n2].y*sc);
    } else {
        __syncthreads();
    }
    __syncthreads();
    float4* T2v = (float4*)(g_T2 + (size_t)(b*Cn+c)*NP);
    for (int j=tid;j<Nn*4;j+=192){
        int n=j>>2, q=j&3;
        float2 a0 = buf[n*SXS + 2*q];
        float2 a1 = buf[n*SXS + 2*q + 1];
        T2v[((size_t)n*Nn + w0)/2 + q] = make_float4(a0.x, a0.y, a1.x, a1.y);
    }
}

// ---------------------------------------------------------------------------
// K3a: 4 coils per block, R3=4 rows, 96 threads; register accumulation,
// one atomicAdd pair per element per coil-group. grid = Bn*4*96 = 1536.
// ---------------------------------------------------------------------------
__global__ void __launch_bounds__(96) k3a_coils()
{
    __shared__ float2 tw[Nn];
    __shared__ float2 buf[BUF3];
    const int tid = threadIdx.x;
    for (int i=tid;i<Nn;i+=96) tw[i]=g_tw[i];
    const int blk = blockIdx.x;
    const int h0 = (blk % 96)*R3;
    const int cg = (blk / 96) % 4;        // coil group
    const int b  =  blk / (96*4);
    const int row=tid/24, k2=tid-row*24;
    float2 acc[16];
    #pragma unroll
    for (int i=0;i<16;i++) acc[i]=make_float2(0.f,0.f);
    __syncthreads();

    const float sc = 1.0f/(float)Nn;
    #pragma unroll
    for (int cc=0;cc<4;cc++){
        int c = cg*4 + cc;
        if (tid < 16*R3){
            int rowA=tid>>4, n1=tid&15;
            const float2* src = g_T2 + (size_t)(b*Cn+c)*NP + (size_t)(h0+rowA)*Nn;
            float2 v[24];
            #pragma unroll
            for (int n2=0;n2<24;n2++) v[n2]=src[n1+16*n2];
            phaseA<true>(v, buf + rowA*EXRS, n1, tw);
        }
        __syncthreads();
        float2 hh[16];
        #pragma unroll
        for (int n1=0;n1<16;n1++) hh[n1]=buf[row*EXRS + k2*17 + n1];
        fft16<true>(hh, tw);
        const float2* cp = g_csm2 + ((size_t)(b*Cn+c))*NP + (size_t)(h0+row)*Nn;
        #pragma unroll
        for (int k1=0;k1<16;k1++){
            int n = k2+24*k1;
            float2 cv = cp[n]; cv.y = -cv.y;      // conj(coil)
            float2 xv = make_float2(hh[k1].x*sc, hh[k1].y*sc);
            float2 p  = cmul(cv, xv);
            acc[k1] = make_float2(acc[k1].x+p.x, acc[k1].y+p.y);
        }
        __syncthreads();
    }
    float* gp = (float*)(g_grad + (size_t)b*NP + (size_t)(h0+row)*Nn);
    #pragma unroll
    for (int k1=0;k1<16;k1++){
        int n = k2+24*k1;
        atomicAdd(gp + 2*n,     acc[k1].x);
        atomicAdd(gp + 2*n + 1, acc[k1].y);
    }
}

// ---------------------------------------------------------------------------
// K3b: pointwise FISTA update + re-zero g_grad for next iteration
// ---------------------------------------------------------------------------
__global__ void __launch_bounds__(256) k3b_fista(const float* __restrict__ zk,
                                                 const float* __restrict__ lam,
                                                 float mu,
                                                 float* __restrict__ out,
                                                 int wout)
{
    int i = blockIdx.x*blockDim.x + threadIdx.x;
    if (i >= Bn*NP) return;
    int b  = i / NP;
    int gi = i - b*NP;
    const float lamv = lam[0];
    float2 grad = g_grad[i];
    g_grad[i] = make_float2(0.f, 0.f);
    float2 yv = g_y[i];
    float2 xo = g_x[i];
    float xnr = yv.x - grad.x;
    float xni = yv.y - grad.y;
    xnr = xnr - lamv*(xnr - zk[(size_t)(b*2+0)*NP + gi]);
    xni = xni - lamv*(xni - zk[(size_t)(b*2+1)*NP + gi]);
    xnr = fmaxf(xnr, 0.f);
    xni = fmaxf(xni, 0.f);
    float ynr = xnr + mu*(xnr - xo.x);
    float yni = xni + mu*(xni - xo.y);
    g_x[i] = make_float2(xnr, xni);
    g_y[i] = make_float2(ynr, yni);
    if (wout) {
        out[(size_t)(b*2+0)*NP + gi] = xnr;
        out[(size_t)(b*2+1)*NP + gi] = xni;
    }
}

// ---------------------------------------------------------------------------
extern "C" void kernel_launch(void* const* d_in, const int* in_sizes, int n_in,
                              void* d_out, int out_size)
{
    const float* z_k = (const float*)d_in[0];
    const float* x0  = (const float*)d_in[1];
    const float* csm = (const float*)d_in[2];
    const float* lam = (const float*)d_in[3];
    const int*   msk = (const int*)  d_in[4];
    float* out = (float*)d_out;

    k0_tw  <<<1, 384>>>();
    k0_init<<<1152, 256>>>(x0, msk);
    k0_csm <<<4608, 256>>>(csm);

    float t = 1.0f;
    const int G12 = Bn*Cn*48;        // 3072
    const int G3a = Bn*4*96;         // 1536
    const int GZ  = (Bn*NP+255)/256; // 2304
    for (int it = 0; it < 20; it++) {
        float tn = (1.0f + sqrtf(1.0f + 4.0f*t*t)) * 0.5f;
        float mu = (t - 1.0f) / tn;
        t = tn;
        k1_fwd_rows<<<G12, 192>>>();
        k2_cols    <<<G12, 192>>>();
        k3a_coils  <<<G3a, 96>>>();
        k3b_fista  <<<GZ, 256>>>(z_k, lam, mu, out, (it == 19) ? 1 : 0);
    }
    (void)in_sizes; (void)n_in; (void)out_size;
}

// round 12
// speedup vs baseline: 1.0787x; 1.0787x over previous
#include <cuda_runtime.h>
#include <math.h>

#define Bn 4
#define Cn 16
#define Nn 384
#define NP (Nn*Nn)

#define R1   8           // rows per block (k1/k2)
#define R3   4           // rows per block (k3a)
#define EXRS 408         // exchange row stride (24*17)
#define EX2RS 401        // second-exchange row stride (16*25 + pad)
#define SXS  9           // transpose-store stride (R1+1)
#define BUF1 3456        // max(8*408, 384*9, 8*401)
#define BUF3 1632        // 4*408 for k3a

// Static device scratch (allocation-free)
__device__ float2 g_T1[(size_t)Bn*Cn*NP];   // [b,c,kw,h]
__device__ float2 g_T2[(size_t)Bn*Cn*NP];   // [b,c,h,kw]
__device__ float2 g_csm2[(size_t)Bn*Cn*NP]; // interleaved csm [b,c,h,w]
__device__ float2 g_x[Bn*NP];
__device__ float2 g_y[Bn*NP];
__device__ float2 g_grad[Bn*NP];
__device__ float4 g_mb[Bn*NP];              // {m, m*br, m*bi, 0}, [b,kw,kh]
__device__ float2 g_tw[Nn];                 // exp(-2*pi*i*k/384)

// Compile-time-indexed constant tables (uniform LDC broadcast — cheap).
__constant__ float2 cW16[10] = {
 {1.f,0.f},{0.9238795325f,-0.3826834324f},{0.7071067812f,-0.7071067812f},
 {0.3826834324f,-0.9238795325f},{0.f,-1.f},{-0.3826834324f,-0.9238795325f},
 {-0.7071067812f,-0.7071067812f},{-0.9238795325f,-0.3826834324f},
 {-1.f,0.f},{-0.9238795325f,0.3826834324f}};
__constant__ float2 cW24[15] = {
 {1.f,0.f},{0.9659258263f,-0.2588190451f},{0.8660254038f,-0.5f},
 {0.7071067812f,-0.7071067812f},{0.5f,-0.8660254038f},{0.2588190451f,-0.9659258263f},
 {0.f,-1.f},{-0.2588190451f,-0.9659258263f},{-0.5f,-0.8660254038f},
 {-0.7071067812f,-0.7071067812f},{-0.8660254038f,-0.5f},{-0.9659258263f,-0.2588190451f},
 {-1.f,0.f},{-0.9659258263f,0.2588190451f},{-0.8660254038f,0.5f}};

__device__ __forceinline__ float2 cmul(float2 a, float2 b){
    return make_float2(fmaf(a.x,b.x,-a.y*b.y), fmaf(a.x,b.y, a.y*b.x));
}
__device__ __forceinline__ float2 cadd(float2 a, float2 b){ return make_float2(a.x+b.x, a.y+b.y); }
__device__ __forceinline__ float2 csub(float2 a, float2 b){ return make_float2(a.x-b.x, a.y-b.y); }

template<bool INV>
__device__ __forceinline__ void fft3(float2& a, float2& b, float2& c){
    const float s = INV ? 0.8660254037844386f : -0.8660254037844386f;
    float2 t = cadd(b,c);
    float2 d = csub(b,c);
    float2 m = make_float2(a.x - 0.5f*t.x, a.y - 0.5f*t.y);
    float2 e = make_float2(-s*d.y, s*d.x);
    a = cadd(a,t);
    b = make_float2(m.x + e.x, m.y + e.y);
    c = make_float2(m.x - e.x, m.y - e.y);
}

template<bool INV>
__device__ __forceinline__ void fft4(float2 v[4]){
    float2 t0=cadd(v[0],v[2]), t1=csub(v[0],v[2]);
    float2 t2=cadd(v[1],v[3]), t3=csub(v[1],v[3]);
    float2 j = INV ? make_float2(-t3.y, t3.x) : make_float2(t3.y, -t3.x);
    v[0]=cadd(t0,t2); v[2]=csub(t0,t2);
    v[1]=cadd(t1,j);  v[3]=csub(t1,j);
}

template<bool INV>
__device__ __forceinline__ void fft8(float2 v[8]){
    float2 e[4]={v[0],v[2],v[4],v[6]}, o[4]={v[1],v[3],v[5],v[7]};
    fft4<INV>(e); fft4<INV>(o);
    const float r=0.70710678118654752f;
    float2 w1 = INV? make_float2(r,r)  : make_float2(r,-r);
    float2 w2 = INV? make_float2(0.f,1.f): make_float2(0.f,-1.f);
    float2 w3 = INV? make_float2(-r,r) : make_float2(-r,-r);
    float2 t;
    t=o[0];          v[0]=cadd(e[0],t); v[4]=csub(e[0],t);
    t=cmul(o[1],w1); v[1]=cadd(e[1],t); v[5]=csub(e[1],t);
    t=cmul(o[2],w2); v[2]=cadd(e[2],t); v[6]=csub(e[2],t);
    t=cmul(o[3],w3); v[3]=cadd(e[3],t); v[7]=csub(e[3],t);
}

template<bool INV>
__device__ __forceinline__ void fft16(float2 v[16]){
    #pragma unroll
    for (int n1=0;n1<4;n1++){
        float2 a[4]={v[n1],v[n1+4],v[n1+8],v[n1+12]};
        fft4<INV>(a);
        v[n1]=a[0]; v[n1+4]=a[1]; v[n1+8]=a[2]; v[n1+12]=a[3];
    }
    float2 out[16];
    #pragma unroll
    for (int k2=0;k2<4;k2++){
        float2 a[4];
        #pragma unroll
        for (int n1=0;n1<4;n1++){
            float2 g = v[n1+4*k2];
            if (k2==0 || n1==0) a[n1]=g;
            else { float2 w=cW16[n1*k2]; if(INV) w.y=-w.y; a[n1]=cmul(g,w); }
        }
        fft4<INV>(a);
        #pragma unroll
        for (int k1=0;k1<4;k1++) out[k2+4*k1]=a[k1];
    }
    #pragma unroll
    for (int i=0;i<16;i++) v[i]=out[i];
}

// Natural-in / natural-out 24-pt FFT in registers (all twiddles compile-time)
template<bool INV>
__device__ __forceinline__ void fft24(float2 v[24], float2 out[24]){
    #pragma unroll
    for (int m1=0;m1<8;m1++) fft3<INV>(v[m1], v[m1+8], v[m1+16]);
    #pragma unroll
    for (int q2=0;q2<3;q2++){
        float2 a[8];
        #pragma unroll
        for (int m1=0;m1<8;m1++){
            float2 g = v[m1+8*q2];
            if (q2==0 || m1==0) a[m1]=g;
            else { float2 w=cW24[m1*q2]; if(INV) w.y=-w.y; a[m1]=cmul(g,w); }
        }
        fft8<INV>(a);
        #pragma unroll
        for (int q1=0;q1<8;q1++) out[q2+3*q1]=a[q1];
    }
}

// 24-pt FFT in registers + W384^{n1*k} twiddle + scatter to exchange buffer
template<bool INV>
__device__ __forceinline__ void phaseA(float2 v[24], float2* exrow, int n1,
                                       const float2* __restrict__ tw)
{
    float2 o[24];
    fft24<INV>(v, o);
    #pragma unroll
    for (int k=0;k<24;k++){
        float2 w = tw[n1*k]; if(INV) w.y=-w.y;
        exrow[k*17 + n1] = cmul(o[k], w);
    }
}

// ---------------------------------------------------------------------------
__global__ void k0_tw()
{
    int i = threadIdx.x;
    if (i < Nn) {
        double th = -2.0 * 3.14159265358979323846 * (double)i / (double)Nn;
        g_tw[i] = make_float2((float)cos(th), (float)sin(th));
    }
}

// zero state + build mask/b pack (merged)
__global__ void k0_init(const float* __restrict__ x0, const int* __restrict__ mask)
{
    for (int i = blockIdx.x*blockDim.x + threadIdx.x; i < Bn*NP; i += gridDim.x*blockDim.x) {
        g_x[i] = make_float2(0.f,0.f);
        g_y[i] = make_float2(0.f,0.f);
        g_grad[i] = make_float2(0.f,0.f);
        int b   = i / NP;
        int rem = i - b*NP;
        int w   = rem / Nn;
        int h   = rem - w*Nn;
        int hi  = h*Nn + w;
        float m = (float)mask[b*NP + hi];
        float xr = x0[(size_t)(2*b  )*NP + hi];
        float xi = x0[(size_t)(2*b+1)*NP + hi];
        g_mb[i] = make_float4(m, m*xr, m*xi, 0.f);
    }
}

// interleave csm once: g_csm2[(b*Cn+c)*NP + p] = {re, im}
__global__ void k0_csm(const float* __restrict__ csm)
{
    for (size_t i = (size_t)blockIdx.x*blockDim.x + threadIdx.x;
         i < (size_t)Bn*Cn*NP; i += (size_t)gridDim.x*blockDim.x) {
        size_t p  = i % NP;
        size_t bc = i / NP;
        size_t c  = bc % Cn;
        size_t b  = bc / Cn;
        float re = csm[((b*2+0)*Cn + c)*NP + p];
        float im = csm[((b*2+1)*Cn + c)*NP + p];
        g_csm2[i] = make_float2(re, im);
    }
}

// ---------------------------------------------------------------------------
// K1: fwd FFT over w of coil*y; transposed write to g_T1[b,c,kw,h]
// ---------------------------------------------------------------------------
__global__ void __launch_bounds__(192,5) k1_fwd_rows()
{
    __shared__ float2 tw[Nn];
    __shared__ float2 buf[BUF1];
    const int tid = threadIdx.x;
    for (int i=tid;i<Nn;i+=192) tw[i]=g_tw[i];
    const int blk = blockIdx.x;
    const int h0 = (blk % 48)*R1;
    const int c  = (blk / 48) % Cn;
    const int b  =  blk / (48*Cn);
    __syncthreads();

    if (tid < 16*R1) {
        int row=tid>>4, n1=tid&15;
        int h=h0+row;
        const float2* cp = g_csm2 + ((size_t)(b*Cn+c))*NP + (size_t)h*Nn;
        const float2* yp = g_y + (size_t)b*NP + (size_t)h*Nn;
        float2 v[24];
        #pragma unroll
        for (int n2=0;n2<24;n2++){
            int n = n1+16*n2;
            v[n2] = cmul(cp[n], yp[n]);
        }
        phaseA<false>(v, buf + row*EXRS, n1, tw);
    }
    __syncthreads();
    {
        int row=tid/24, k2=tid-row*24;
        float2 hh[16];
        #pragma unroll
        for (int n1=0;n1<16;n1++) hh[n1]=buf[row*EXRS + k2*17 + n1];
        fft16<false>(hh);
        __syncthreads();
        #pragma unroll
        for (int k1=0;k1<16;k1++) buf[(k2+24*k1)*SXS + row] = hh[k1];
    }
    __syncthreads();
    // vectorized writeout: 4 float4 per k (rows h0..h0+7 are consecutive)
    float4* T1v = (float4*)(g_T1 + (size_t)(b*Cn+c)*NP);
    for (int j=tid;j<Nn*4;j+=192){
        int k=j>>2, q=j&3;
        float2 a0 = buf[k*SXS + 2*q];
        float2 a1 = buf[k*SXS + 2*q + 1];
        T1v[((size_t)k*Nn + h0)/2 + q] = make_float4(a0.x, a0.y, a1.x, a1.y);
    }
}

// ---------------------------------------------------------------------------
// K2: fwd FFT over h, mask & subtract, reverse-network inv FFT over h.
// Reads g_T1[b,c,kw,h]; writes g_T2[b,c,h,kw] (scaled 1/384).
// ---------------------------------------------------------------------------
__global__ void __launch_bounds__(192,5) k2_cols()
{
    __shared__ float2 tw[Nn];
    __shared__ float2 buf[BUF1];
    const int tid = threadIdx.x;
    for (int i=tid;i<Nn;i+=192) tw[i]=g_tw[i];
    const int blk = blockIdx.x;
    const int w0 = (blk % 48)*R1;
    const int c  = (blk / 48) % Cn;
    const int b  =  blk / (48*Cn);
    __syncthreads();

    // phase 1: load + fwd phaseA (128 threads)
    const float2* T1 = g_T1 + (size_t)(b*Cn+c)*NP;
    if (tid < 16*R1){
        int rowA=tid>>4, n1=tid&15;
        const float2* src = T1 + (size_t)(w0+rowA)*Nn;
        float2 v[24];
        #pragma unroll
        for (int n2=0;n2<24;n2++) v[n2]=src[n1+16*n2];
        phaseA<false>(v, buf + rowA*EXRS, n1, tw);
    }
    __syncthreads();

    // phase 2: fft16 fwd, mask, fft16 inv (registers), conj twiddle
    const int row=tid/24, k2=tid-row*24;
    float2 hh[16];
    #pragma unroll
    for (int n1=0;n1<16;n1++) hh[n1]=buf[row*EXRS + k2*17 + n1];
    fft16<false>(hh);
    {
        int w = w0+row;
        const float4* mb = g_mb + (size_t)b*NP + (size_t)w*Nn;
        #pragma unroll
        for (int k1=0;k1<16;k1++){
            int k = k2+24*k1;
            float4 q = mb[k];
            hh[k1] = make_float2(q.x*hh[k1].x - q.y, q.x*hh[k1].y - q.z);
        }
    }
    fft16<true>(hh);          // inner inverse over k1; hh now indexed by n1
    __syncthreads();
    #pragma unroll
    for (int n1=0;n1<16;n1++){
        float2 wv = tw[n1*k2]; wv.y = -wv.y;     // W384^{+n1*k2}
        buf[row*EX2RS + n1*25 + k2] = cmul(hh[n1], wv);
    }
    __syncthreads();

    // phase 3: fft24 inverse over k2 (128 threads), scale, transpose store
    if (tid < 16*R1){
        int rowA=tid>>4, n1=tid&15;
        float2 u[24], xr[24];
        #pragma unroll
        for (int j2=0;j2<24;j2++) u[j2]=buf[rowA*EX2RS + n1*25 + j2];
        fft24<true>(u, xr);
        __syncthreads();
        const float sc = 1.0f/(float)Nn;
        #pragma unroll
        for (int n2=0;n2<24;n2++)
            buf[(n1+16*n2)*SXS + rowA] = make_float2(xr[n2].x*sc, xr[n2].y*sc);
    } else {
        __syncthreads();
    }
    __syncthreads();
    float4* T2v = (float4*)(g_T2 + (size_t)(b*Cn+c)*NP);
    for (int j=tid;j<Nn*4;j+=192){
        int n=j>>2, q=j&3;
        float2 a0 = buf[n*SXS + 2*q];
        float2 a1 = buf[n*SXS + 2*q + 1];
        T2v[((size_t)n*Nn + w0)/2 + q] = make_float4(a0.x, a0.y, a1.x, a1.y);
    }
}

// ---------------------------------------------------------------------------
// K3a: 4 coils per block, R3=4 rows, 96 threads; register accumulation,
// one atomicAdd pair per element per coil-group. grid = Bn*4*96 = 1536.
// ---------------------------------------------------------------------------
__global__ void __launch_bounds__(96) k3a_coils()
{
    __shared__ float2 tw[Nn];
    __shared__ float2 buf[BUF3];
    const int tid = threadIdx.x;
    for (int i=tid;i<Nn;i+=96) tw[i]=g_tw[i];
    const int blk = blockIdx.x;
    const int h0 = (blk % 96)*R3;
    const int cg = (blk / 96) % 4;        // coil group
    const int b  =  blk / (96*4);
    const int row=tid/24, k2=tid-row*24;
    float2 acc[16];
    #pragma unroll
    for (int i=0;i<16;i++) acc[i]=make_float2(0.f,0.f);
    __syncthreads();

    const float sc = 1.0f/(float)Nn;
    #pragma unroll
    for (int cc=0;cc<4;cc++){
        int c = cg*4 + cc;
        if (tid < 16*R3){
            int rowA=tid>>4, n1=tid&15;
            const float2* src = g_T2 + (size_t)(b*Cn+c)*NP + (size_t)(h0+rowA)*Nn;
            float2 v[24];
            #pragma unroll
            for (int n2=0;n2<24;n2++) v[n2]=src[n1+16*n2];
            phaseA<true>(v, buf + rowA*EXRS, n1, tw);
        }
        __syncthreads();
        float2 hh[16];
        #pragma unroll
        for (int n1=0;n1<16;n1++) hh[n1]=buf[row*EXRS + k2*17 + n1];
        fft16<true>(hh);
        const float2* cp = g_csm2 + ((size_t)(b*Cn+c))*NP + (size_t)(h0+row)*Nn;
        #pragma unroll
        for (int k1=0;k1<16;k1++){
            int n = k2+24*k1;
            float2 cv = cp[n]; cv.y = -cv.y;      // conj(coil)
            float2 xv = make_float2(hh[k1].x*sc, hh[k1].y*sc);
            float2 p  = cmul(cv, xv);
            acc[k1] = make_float2(acc[k1].x+p.x, acc[k1].y+p.y);
        }
        __syncthreads();
    }
    float* gp = (float*)(g_grad + (size_t)b*NP + (size_t)(h0+row)*Nn);
    #pragma unroll
    for (int k1=0;k1<16;k1++){
        int n = k2+24*k1;
        atomicAdd(gp + 2*n,     acc[k1].x);
        atomicAdd(gp + 2*n + 1, acc[k1].y);
    }
}

// ---------------------------------------------------------------------------
// K3b: pointwise FISTA update + re-zero g_grad for next iteration
// ---------------------------------------------------------------------------
__global__ void __launch_bounds__(256) k3b_fista(const float* __restrict__ zk,
                                                 const float* __restrict__ lam,
                                                 float mu,
                                                 float* __restrict__ out,
                                                 int wout)
{
    int i = blockIdx.x*blockDim.x + threadIdx.x;
    if (i >= Bn*NP) return;
    int b  = i / NP;
    int gi = i - b*NP;
    const float lamv = lam[0];
    float2 grad = g_grad[i];
    g_grad[i] = make_float2(0.f, 0.f);
    float2 yv = g_y[i];
    float2 xo = g_x[i];
    float xnr = yv.x - grad.x;
    float xni = yv.y - grad.y;
    xnr = xnr - lamv*(xnr - zk[(size_t)(b*2+0)*NP + gi]);
    xni = xni - lamv*(xni - zk[(size_t)(b*2+1)*NP + gi]);
    xnr = fmaxf(xnr, 0.f);
    xni = fmaxf(xni, 0.f);
    float ynr = xnr + mu*(xnr - xo.x);
    float yni = xni + mu*(xni - xo.y);
    g_x[i] = make_float2(xnr, xni);
    g_y[i] = make_float2(ynr, yni);
    if (wout) {
        out[(size_t)(b*2+0)*NP + gi] = xnr;
        out[(size_t)(b*2+1)*NP + gi] = xni;
    }
}

// ---------------------------------------------------------------------------
extern "C" void kernel_launch(void* const* d_in, const int* in_sizes, int n_in,
                              void* d_out, int out_size)
{
    const float* z_k = (const float*)d_in[0];
    const float* x0  = (const float*)d_in[1];
    const float* csm = (const float*)d_in[2];
    const float* lam = (const float*)d_in[3];
    const int*   msk = (const int*)  d_in[4];
    float* out = (float*)d_out;

    k0_tw  <<<1, 384>>>();
    k0_init<<<1152, 256>>>(x0, msk);
    k0_csm <<<4608, 256>>>(csm);

    float t = 1.0f;
    const int G12 = Bn*Cn*48;        // 3072
    const int G3a = Bn*4*96;         // 1536
    const int GZ  = (Bn*NP+255)/256; // 2304
    for (int it = 0; it < 20; it++) {
        float tn = (1.0f + sqrtf(1.0f + 4.0f*t*t)) * 0.5f;
        float mu = (t - 1.0f) / tn;
        t = tn;
        k1_fwd_rows<<<G12, 192>>>();
        k2_cols    <<<G12, 192>>>();
        k3a_coils  <<<G3a, 96>>>();
        k3b_fista  <<<GZ, 256>>>(z_k, lam, mu, out, (it == 19) ? 1 : 0);
    }
    (void)in_sizes; (void)n_in; (void)out_size;
}

// round 13
// speedup vs baseline: 1.1320x; 1.0494x over previous
#include <cuda_runtime.h>
#include <math.h>

#define Bn 4
#define Cn 16
#define Nn 384
#define NP (Nn*Nn)

#define R1   8           // rows per block (k1/k2)
#define R3   4           // rows per block (k3a)
#define EXRS 408         // exchange row stride (24*17)
#define EX2RS 401        // second-exchange row stride (16*25 + pad)
#define SXS  9           // transpose-store stride (R1+1)
#define BUF1 3456        // max(8*408, 384*9, 8*401)
#define BUF3 1632        // 4*408 for k3a

// Static device scratch (allocation-free)
__device__ float2 g_T1[(size_t)Bn*Cn*NP];   // [b,c,kw,h]
__device__ float2 g_T2[(size_t)Bn*Cn*NP];   // [b,c,h,kw]
__device__ float2 g_csm2[(size_t)Bn*Cn*NP]; // interleaved csm [b,c,h,w]
__device__ float2 g_x[Bn*NP];
__device__ float2 g_y[Bn*NP];
__device__ float2 g_grad[Bn*NP];
__device__ float4 g_mb[Bn*NP];              // {m, m*br, m*bi, 0}, [b,kw,kh]
__device__ float2 g_tw[Nn];                 // exp(-2*pi*i*k/384)

// Compile-time-indexed constant tables (uniform LDC broadcast — cheap).
__constant__ float2 cW16[10] = {
 {1.f,0.f},{0.9238795325f,-0.3826834324f},{0.7071067812f,-0.7071067812f},
 {0.3826834324f,-0.9238795325f},{0.f,-1.f},{-0.3826834324f,-0.9238795325f},
 {-0.7071067812f,-0.7071067812f},{-0.9238795325f,-0.3826834324f},
 {-1.f,0.f},{-0.9238795325f,0.3826834324f}};
__constant__ float2 cW24[15] = {
 {1.f,0.f},{0.9659258263f,-0.2588190451f},{0.8660254038f,-0.5f},
 {0.7071067812f,-0.7071067812f},{0.5f,-0.8660254038f},{0.2588190451f,-0.9659258263f},
 {0.f,-1.f},{-0.2588190451f,-0.9659258263f},{-0.5f,-0.8660254038f},
 {-0.7071067812f,-0.7071067812f},{-0.8660254038f,-0.5f},{-0.9659258263f,-0.2588190451f},
 {-1.f,0.f},{-0.9659258263f,0.2588190451f},{-0.8660254038f,0.5f}};

__device__ __forceinline__ float2 cmul(float2 a, float2 b){
    return make_float2(fmaf(a.x,b.x,-a.y*b.y), fmaf(a.x,b.y, a.y*b.x));
}
__device__ __forceinline__ float2 cadd(float2 a, float2 b){ return make_float2(a.x+b.x, a.y+b.y); }
__device__ __forceinline__ float2 csub(float2 a, float2 b){ return make_float2(a.x-b.x, a.y-b.y); }

__device__ __forceinline__ float2 ldcs2(const float2* p){
    float4 dummy;
    float2 r;
    asm volatile("ld.global.cs.v2.f32 {%0,%1}, [%2];" : "=f"(r.x), "=f"(r.y) : "l"(p));
    (void)dummy;
    return r;
}

template<bool INV>
__device__ __forceinline__ void fft3(float2& a, float2& b, float2& c){
    const float s = INV ? 0.8660254037844386f : -0.8660254037844386f;
    float2 t = cadd(b,c);
    float2 d = csub(b,c);
    float2 m = make_float2(a.x - 0.5f*t.x, a.y - 0.5f*t.y);
    float2 e = make_float2(-s*d.y, s*d.x);
    a = cadd(a,t);
    b = make_float2(m.x + e.x, m.y + e.y);
    c = make_float2(m.x - e.x, m.y - e.y);
}

template<bool INV>
__device__ __forceinline__ void fft4(float2 v[4]){
    float2 t0=cadd(v[0],v[2]), t1=csub(v[0],v[2]);
    float2 t2=cadd(v[1],v[3]), t3=csub(v[1],v[3]);
    float2 j = INV ? make_float2(-t3.y, t3.x) : make_float2(t3.y, -t3.x);
    v[0]=cadd(t0,t2); v[2]=csub(t0,t2);
    v[1]=cadd(t1,j);  v[3]=csub(t1,j);
}

template<bool INV>
__device__ __forceinline__ void fft8(float2 v[8]){
    float2 e[4]={v[0],v[2],v[4],v[6]}, o[4]={v[1],v[3],v[5],v[7]};
    fft4<INV>(e); fft4<INV>(o);
    const float r=0.70710678118654752f;
    float2 w1 = INV? make_float2(r,r)  : make_float2(r,-r);
    float2 w2 = INV? make_float2(0.f,1.f): make_float2(0.f,-1.f);
    float2 w3 = INV? make_float2(-r,r) : make_float2(-r,-r);
    float2 t;
    t=o[0];          v[0]=cadd(e[0],t); v[4]=csub(e[0],t);
    t=cmul(o[1],w1); v[1]=cadd(e[1],t); v[5]=csub(e[1],t);
    t=cmul(o[2],w2); v[2]=cadd(e[2],t); v[6]=csub(e[2],t);
    t=cmul(o[3],w3); v[3]=cadd(e[3],t); v[7]=csub(e[3],t);
}

template<bool INV>
__device__ __forceinline__ void fft16(float2 v[16]){
    #pragma unroll
    for (int n1=0;n1<4;n1++){
        float2 a[4]={v[n1],v[n1+4],v[n1+8],v[n1+12]};
        fft4<INV>(a);
        v[n1]=a[0]; v[n1+4]=a[1]; v[n1+8]=a[2]; v[n1+12]=a[3];
    }
    float2 out[16];
    #pragma unroll
    for (int k2=0;k2<4;k2++){
        float2 a[4];
        #pragma unroll
        for (int n1=0;n1<4;n1++){
            float2 g = v[n1+4*k2];
            if (k2==0 || n1==0) a[n1]=g;
            else { float2 w=cW16[n1*k2]; if(INV) w.y=-w.y; a[n1]=cmul(g,w); }
        }
        fft4<INV>(a);
        #pragma unroll
        for (int k1=0;k1<4;k1++) out[k2+4*k1]=a[k1];
    }
    #pragma unroll
    for (int i=0;i<16;i++) v[i]=out[i];
}

// Natural-in / natural-out 24-pt FFT in registers (all twiddles compile-time)
template<bool INV>
__device__ __forceinline__ void fft24(float2 v[24], float2 out[24]){
    #pragma unroll
    for (int m1=0;m1<8;m1++) fft3<INV>(v[m1], v[m1+8], v[m1+16]);
    #pragma unroll
    for (int q2=0;q2<3;q2++){
        float2 a[8];
        #pragma unroll
        for (int m1=0;m1<8;m1++){
            float2 g = v[m1+8*q2];
            if (q2==0 || m1==0) a[m1]=g;
            else { float2 w=cW24[m1*q2]; if(INV) w.y=-w.y; a[m1]=cmul(g,w); }
        }
        fft8<INV>(a);
        #pragma unroll
        for (int q1=0;q1<8;q1++) out[q2+3*q1]=a[q1];
    }
}

// 24-pt FFT in registers + W384^{n1*k} twiddle + scatter to exchange buffer
template<bool INV>
__device__ __forceinline__ void phaseA(float2 v[24], float2* exrow, int n1,
                                       const float2* __restrict__ tw)
{
    float2 o[24];
    fft24<INV>(v, o);
    #pragma unroll
    for (int k=0;k<24;k++){
        float2 w = tw[n1*k]; if(INV) w.y=-w.y;
        exrow[k*17 + n1] = cmul(o[k], w);
    }
}

// ---------------------------------------------------------------------------
__global__ void k0_tw()
{
    int i = threadIdx.x;
    if (i < Nn) {
        double th = -2.0 * 3.14159265358979323846 * (double)i / (double)Nn;
        g_tw[i] = make_float2((float)cos(th), (float)sin(th));
    }
}

// zero state + build mask/b pack (merged)
__global__ void k0_init(const float* __restrict__ x0, const int* __restrict__ mask)
{
    for (int i = blockIdx.x*blockDim.x + threadIdx.x; i < Bn*NP; i += gridDim.x*blockDim.x) {
        g_x[i] = make_float2(0.f,0.f);
        g_y[i] = make_float2(0.f,0.f);
        g_grad[i] = make_float2(0.f,0.f);
        int b   = i / NP;
        int rem = i - b*NP;
        int w   = rem / Nn;
        int h   = rem - w*Nn;
        int hi  = h*Nn + w;
        float m = (float)mask[b*NP + hi];
        float xr = x0[(size_t)(2*b  )*NP + hi];
        float xi = x0[(size_t)(2*b+1)*NP + hi];
        g_mb[i] = make_float4(m, m*xr, m*xi, 0.f);
    }
}

// interleave csm once: g_csm2[(b*Cn+c)*NP + p] = {re, im}
__global__ void k0_csm(const float* __restrict__ csm)
{
    for (size_t i = (size_t)blockIdx.x*blockDim.x + threadIdx.x;
         i < (size_t)Bn*Cn*NP; i += (size_t)gridDim.x*blockDim.x) {
        size_t p  = i % NP;
        size_t bc = i / NP;
        size_t c  = bc % Cn;
        size_t b  = bc / Cn;
        float re = csm[((b*2+0)*Cn + c)*NP + p];
        float im = csm[((b*2+1)*Cn + c)*NP + p];
        g_csm2[i] = make_float2(re, im);
    }
}

// ---------------------------------------------------------------------------
// K1: fwd FFT over w of coil*y; transposed write to g_T1[b,c,kw,h]
// csm read with evict-first streaming policy (read-once, keep L2 for T1).
// ---------------------------------------------------------------------------
__global__ void __launch_bounds__(192,5) k1_fwd_rows()
{
    __shared__ float2 tw[Nn];
    __shared__ float2 buf[BUF1];
    const int tid = threadIdx.x;
    for (int i=tid;i<Nn;i+=192) tw[i]=g_tw[i];
    const int blk = blockIdx.x;
    const int h0 = (blk % 48)*R1;
    const int c  = (blk / 48) % Cn;
    const int b  =  blk / (48*Cn);
    __syncthreads();

    if (tid < 16*R1) {
        int row=tid>>4, n1=tid&15;
        int h=h0+row;
        const float2* cp = g_csm2 + ((size_t)(b*Cn+c))*NP + (size_t)h*Nn;
        const float2* yp = g_y + (size_t)b*NP + (size_t)h*Nn;
        float2 v[24];
        #pragma unroll
        for (int n2=0;n2<24;n2++){
            int n = n1+16*n2;
            v[n2] = cmul(ldcs2(cp+n), yp[n]);
        }
        phaseA<false>(v, buf + row*EXRS, n1, tw);
    }
    __syncthreads();
    {
        int row=tid/24, k2=tid-row*24;
        float2 hh[16];
        #pragma unroll
        for (int n1=0;n1<16;n1++) hh[n1]=buf[row*EXRS + k2*17 + n1];
        fft16<false>(hh);
        __syncthreads();
        #pragma unroll
        for (int k1=0;k1<16;k1++) buf[(k2+24*k1)*SXS + row] = hh[k1];
    }
    __syncthreads();
    // vectorized writeout: 4 float4 per k (rows h0..h0+7 are consecutive)
    float4* T1v = (float4*)(g_T1 + (size_t)(b*Cn+c)*NP);
    for (int j=tid;j<Nn*4;j+=192){
        int k=j>>2, q=j&3;
        float2 a0 = buf[k*SXS + 2*q];
        float2 a1 = buf[k*SXS + 2*q + 1];
        T1v[((size_t)k*Nn + h0)/2 + q] = make_float4(a0.x, a0.y, a1.x, a1.y);
    }
}

// ---------------------------------------------------------------------------
// K2: fwd FFT over h, mask & subtract, reverse-network inv FFT over h.
// Reads g_T1[b,c,kw,h] (streaming — read-once); writes g_T2[b,c,h,kw].
// ---------------------------------------------------------------------------
__global__ void __launch_bounds__(192,5) k2_cols()
{
    __shared__ float2 tw[Nn];
    __shared__ float2 buf[BUF1];
    const int tid = threadIdx.x;
    for (int i=tid;i<Nn;i+=192) tw[i]=g_tw[i];
    const int blk = blockIdx.x;
    const int w0 = (blk % 48)*R1;
    const int c  = (blk / 48) % Cn;
    const int b  =  blk / (48*Cn);
    __syncthreads();

    // phase 1: load + fwd phaseA (128 threads)
    const float2* T1 = g_T1 + (size_t)(b*Cn+c)*NP;
    if (tid < 16*R1){
        int rowA=tid>>4, n1=tid&15;
        const float2* src = T1 + (size_t)(w0+rowA)*Nn;
        float2 v[24];
        #pragma unroll
        for (int n2=0;n2<24;n2++) v[n2]=ldcs2(src + n1+16*n2);
        phaseA<false>(v, buf + rowA*EXRS, n1, tw);
    }
    __syncthreads();

    // phase 2: fft16 fwd, mask, fft16 inv (registers), conj twiddle
    const int row=tid/24, k2=tid-row*24;
    float2 hh[16];
    #pragma unroll
    for (int n1=0;n1<16;n1++) hh[n1]=buf[row*EXRS + k2*17 + n1];
    fft16<false>(hh);
    {
        int w = w0+row;
        const float4* mb = g_mb + (size_t)b*NP + (size_t)w*Nn;
        #pragma unroll
        for (int k1=0;k1<16;k1++){
            int k = k2+24*k1;
            float4 q = mb[k];
            hh[k1] = make_float2(q.x*hh[k1].x - q.y, q.x*hh[k1].y - q.z);
        }
    }
    fft16<true>(hh);          // inner inverse over k1; hh now indexed by n1
    __syncthreads();
    #pragma unroll
    for (int n1=0;n1<16;n1++){
        float2 wv = tw[n1*k2]; wv.y = -wv.y;     // W384^{+n1*k2}
        buf[row*EX2RS + n1*25 + k2] = cmul(hh[n1], wv);
    }
    __syncthreads();

    // phase 3: fft24 inverse over k2 (128 threads), scale, transpose store
    if (tid < 16*R1){
        int rowA=tid>>4, n1=tid&15;
        float2 u[24], xr[24];
        #pragma unroll
        for (int j2=0;j2<24;j2++) u[j2]=buf[rowA*EX2RS + n1*25 + j2];
        fft24<true>(u, xr);
        __syncthreads();
        const float sc = 1.0f/(float)Nn;
        #pragma unroll
        for (int n2=0;n2<24;n2++)
            buf[(n1+16*n2)*SXS + rowA] = make_float2(xr[n2].x*sc, xr[n2].y*sc);
    } else {
        __syncthreads();
    }
    __syncthreads();
    float4* T2v = (float4*)(g_T2 + (size_t)(b*Cn+c)*NP);
    for (int j=tid;j<Nn*4;j+=192){
        int n=j>>2, q=j&3;
        float2 a0 = buf[n*SXS + 2*q];
        float2 a1 = buf[n*SXS + 2*q + 1];
        T2v[((size_t)n*Nn + w0)/2 + q] = make_float4(a0.x, a0.y, a1.x, a1.y);
    }
}

// ---------------------------------------------------------------------------
// K3a: 4 coils per block, R3=4 rows, 96 threads; register accumulation,
// one atomicAdd pair per element per coil-group. grid = Bn*4*96 = 1536.
// T2 and csm read with streaming policy (both read-once here).
// ---------------------------------------------------------------------------
__global__ void __launch_bounds__(96) k3a_coils()
{
    __shared__ float2 tw[Nn];
    __shared__ float2 buf[BUF3];
    const int tid = threadIdx.x;
    for (int i=tid;i<Nn;i+=96) tw[i]=g_tw[i];
    const int blk = blockIdx.x;
    const int h0 = (blk % 96)*R3;
    const int cg = (blk / 96) % 4;        // coil group
    const int b  =  blk / (96*4);
    const int row=tid/24, k2=tid-row*24;
    float2 acc[16];
    #pragma unroll
    for (int i=0;i<16;i++) acc[i]=make_float2(0.f,0.f);
    __syncthreads();

    const float sc = 1.0f/(float)Nn;
    #pragma unroll
    for (int cc=0;cc<4;cc++){
        int c = cg*4 + cc;
        if (tid < 16*R3){
            int rowA=tid>>4, n1=tid&15;
            const float2* src = g_T2 + (size_t)(b*Cn+c)*NP + (size_t)(h0+rowA)*Nn;
            float2 v[24];
            #pragma unroll
            for (int n2=0;n2<24;n2++) v[n2]=ldcs2(src + n1+16*n2);
            phaseA<true>(v, buf + rowA*EXRS, n1, tw);
        }
        __syncthreads();
        float2 hh[16];
        #pragma unroll
        for (int n1=0;n1<16;n1++) hh[n1]=buf[row*EXRS + k2*17 + n1];
        fft16<true>(hh);
        const float2* cp = g_csm2 + ((size_t)(b*Cn+c))*NP + (size_t)(h0+row)*Nn;
        #pragma unroll
        for (int k1=0;k1<16;k1++){
            int n = k2+24*k1;
            float2 cv = ldcs2(cp + n); cv.y = -cv.y;   // conj(coil)
            float2 xv = make_float2(hh[k1].x*sc, hh[k1].y*sc);
            float2 p  = cmul(cv, xv);
            acc[k1] = make_float2(acc[k1].x+p.x, acc[k1].y+p.y);
        }
        __syncthreads();
    }
    float* gp = (float*)(g_grad + (size_t)b*NP + (size_t)(h0+row)*Nn);
    #pragma unroll
    for (int k1=0;k1<16;k1++){
        int n = k2+24*k1;
        atomicAdd(gp + 2*n,     acc[k1].x);
        atomicAdd(gp + 2*n + 1, acc[k1].y);
    }
}

// ---------------------------------------------------------------------------
// K3b: pointwise FISTA update + re-zero g_grad for next iteration
// ---------------------------------------------------------------------------
__global__ void __launch_bounds__(256) k3b_fista(const float* __restrict__ zk,
                                                 const float* __restrict__ lam,
                                                 float mu,
                                                 float* __restrict__ out,
                                                 int wout)
{
    int i = blockIdx.x*blockDim.x + threadIdx.x;
    if (i >= Bn*NP) return;
    int b  = i / NP;
    int gi = i - b*NP;
    const float lamv = lam[0];
    float2 grad = g_grad[i];
    g_grad[i] = make_float2(0.f, 0.f);
    float2 yv = g_y[i];
    float2 xo = g_x[i];
    float xnr = yv.x - grad.x;
    float xni = yv.y - grad.y;
    xnr = xnr - lamv*(xnr - zk[(size_t)(b*2+0)*NP + gi]);
    xni = xni - lamv*(xni - zk[(size_t)(b*2+1)*NP + gi]);
    xnr = fmaxf(xnr, 0.f);
    xni = fmaxf(xni, 0.f);
    float ynr = xnr + mu*(xnr - xo.x);
    float yni = xni + mu*(xni - xo.y);
    g_x[i] = make_float2(xnr, xni);
    g_y[i] = make_float2(ynr, yni);
    if (wout) {
        out[(size_t)(b*2+0)*NP + gi] = xnr;
        out[(size_t)(b*2+1)*NP + gi] = xni;
    }
}

// ---------------------------------------------------------------------------
extern "C" void kernel_launch(void* const* d_in, const int* in_sizes, int n_in,
                              void* d_out, int out_size)
{
    const float* z_k = (const float*)d_in[0];
    const float* x0  = (const float*)d_in[1];
    const float* csm = (const float*)d_in[2];
    const float* lam = (const float*)d_in[3];
    const int*   msk = (const int*)  d_in[4];
    float* out = (float*)d_out;

    k0_tw  <<<1, 384>>>();
    k0_init<<<1152, 256>>>(x0, msk);
    k0_csm <<<4608, 256>>>(csm);

    float t = 1.0f;
    const int G12 = Bn*Cn*48;        // 3072
    const int G3a = Bn*4*96;         // 1536
    const int GZ  = (Bn*NP+255)/256; // 2304
    for (int it = 0; it < 20; it++) {
        float tn = (1.0f + sqrtf(1.0f + 4.0f*t*t)) * 0.5f;
        float mu = (t - 1.0f) / tn;
        t = tn;
        k1_fwd_rows<<<G12, 192>>>();
        k2_cols    <<<G12, 192>>>();
        k3a_coils  <<<G3a, 96>>>();
        k3b_fista  <<<GZ, 256>>>(z_k, lam, mu, out, (it == 19) ? 1 : 0);
    }
    (void)in_sizes; (void)n_in; (void)out_size;
}

// round 15
// speedup vs baseline: 1.1767x; 1.0395x over previous
#include <cuda_runtime.h>
#include <math.h>

#define Bn 4
#define Cn 16
#define Nn 384
#define NP (Nn*Nn)

#define R1   8           // rows per block (k1/k2)
#define R3   4           // rows per block (k3a)
#define EXRS 409         // exchange row stride (24*17, +1 for row-inner spread)
#define EX2RS 401        // second-exchange row stride (16*25 + pad)
#define BUF1 3272        // 8*409
#define BUF3 1636        // 4*409 for k3a

// Static device scratch (allocation-free)
__device__ float2 g_T1[(size_t)Bn*Cn*NP];   // [b,c,kw,h]
__device__ float2 g_T2[(size_t)Bn*Cn*NP];   // [b,c,h,kw]
__device__ float2 g_csm2[(size_t)Bn*Cn*NP]; // interleaved csm [b,c,h,w]
__device__ float2 g_x[Bn*NP];
__device__ float2 g_y[Bn*NP];
__device__ float2 g_grad[Bn*NP];
__device__ float4 g_mb[Bn*NP];              // {m, m*br, m*bi, 0}, [b,kw,kh]
__device__ float2 g_tw[Nn];                 // exp(-2*pi*i*k/384)

// Compile-time-indexed constant tables (uniform LDC broadcast — cheap).
__constant__ float2 cW16[10] = {
 {1.f,0.f},{0.9238795325f,-0.3826834324f},{0.7071067812f,-0.7071067812f},
 {0.3826834324f,-0.9238795325f},{0.f,-1.f},{-0.3826834324f,-0.9238795325f},
 {-0.7071067812f,-0.7071067812f},{-0.9238795325f,-0.3826834324f},
 {-1.f,0.f},{-0.9238795325f,0.3826834324f}};
__constant__ float2 cW24[15] = {
 {1.f,0.f},{0.9659258263f,-0.2588190451f},{0.8660254038f,-0.5f},
 {0.7071067812f,-0.7071067812f},{0.5f,-0.8660254038f},{0.2588190451f,-0.9659258263f},
 {0.f,-1.f},{-0.2588190451f,-0.9659258263f},{-0.5f,-0.8660254038f},
 {-0.7071067812f,-0.7071067812f},{-0.8660254038f,-0.5f},{-0.9659258263f,-0.2588190451f},
 {-1.f,0.f},{-0.9659258263f,0.2588190451f},{-0.8660254038f,0.5f}};

__device__ __forceinline__ float2 cmul(float2 a, float2 b){
    return make_float2(fmaf(a.x,b.x,-a.y*b.y), fmaf(a.x,b.y, a.y*b.x));
}
__device__ __forceinline__ float2 cadd(float2 a, float2 b){ return make_float2(a.x+b.x, a.y+b.y); }
__device__ __forceinline__ float2 csub(float2 a, float2 b){ return make_float2(a.x-b.x, a.y-b.y); }

__device__ __forceinline__ float2 ldcs2(const float2* p){
    float2 r;
    asm volatile("ld.global.cs.v2.f32 {%0,%1}, [%2];" : "=f"(r.x), "=f"(r.y) : "l"(p));
    return r;
}

template<bool INV>
__device__ __forceinline__ void fft3(float2& a, float2& b, float2& c){
    const float s = INV ? 0.8660254037844386f : -0.8660254037844386f;
    float2 t = cadd(b,c);
    float2 d = csub(b,c);
    float2 m = make_float2(a.x - 0.5f*t.x, a.y - 0.5f*t.y);
    float2 e = make_float2(-s*d.y, s*d.x);
    a = cadd(a,t);
    b = make_float2(m.x + e.x, m.y + e.y);
    c = make_float2(m.x - e.x, m.y - e.y);
}

template<bool INV>
__device__ __forceinline__ void fft4(float2 v[4]){
    float2 t0=cadd(v[0],v[2]), t1=csub(v[0],v[2]);
    float2 t2=cadd(v[1],v[3]), t3=csub(v[1],v[3]);
    float2 j = INV ? make_float2(-t3.y, t3.x) : make_float2(t3.y, -t3.x);
    v[0]=cadd(t0,t2); v[2]=csub(t0,t2);
    v[1]=cadd(t1,j);  v[3]=csub(t1,j);
}

template<bool INV>
__device__ __forceinline__ void fft8(float2 v[8]){
    float2 e[4]={v[0],v[2],v[4],v[6]}, o[4]={v[1],v[3],v[5],v[7]};
    fft4<INV>(e); fft4<INV>(o);
    const float r=0.70710678118654752f;
    float2 w1 = INV? make_float2(r,r)  : make_float2(r,-r);
    float2 w2 = INV? make_float2(0.f,1.f): make_float2(0.f,-1.f);
    float2 w3 = INV? make_float2(-r,r) : make_float2(-r,-r);
    float2 t;
    t=o[0];          v[0]=cadd(e[0],t); v[4]=csub(e[0],t);
    t=cmul(o[1],w1); v[1]=cadd(e[1],t); v[5]=csub(e[1],t);
    t=cmul(o[2],w2); v[2]=cadd(e[2],t); v[6]=csub(e[2],t);
    t=cmul(o[3],w3); v[3]=cadd(e[3],t); v[7]=csub(e[3],t);
}

template<bool INV>
__device__ __forceinline__ void fft16(float2 v[16]){
    #pragma unroll
    for (int n1=0;n1<4;n1++){
        float2 a[4]={v[n1],v[n1+4],v[n1+8],v[n1+12]};
        fft4<INV>(a);
        v[n1]=a[0]; v[n1+4]=a[1]; v[n1+8]=a[2]; v[n1+12]=a[3];
    }
    float2 out[16];
    #pragma unroll
    for (int k2=0;k2<4;k2++){
        float2 a[4];
        #pragma unroll
        for (int n1=0;n1<4;n1++){
            float2 g = v[n1+4*k2];
            if (k2==0 || n1==0) a[n1]=g;
            else { float2 w=cW16[n1*k2]; if(INV) w.y=-w.y; a[n1]=cmul(g,w); }
        }
        fft4<INV>(a);
        #pragma unroll
        for (int k1=0;k1<4;k1++) out[k2+4*k1]=a[k1];
    }
    #pragma unroll
    for (int i=0;i<16;i++) v[i]=out[i];
}

// Natural-in / natural-out 24-pt FFT in registers (all twiddles compile-time)
template<bool INV>
__device__ __forceinline__ void fft24(float2 v[24], float2 out[24]){
    #pragma unroll
    for (int m1=0;m1<8;m1++) fft3<INV>(v[m1], v[m1+8], v[m1+16]);
    #pragma unroll
    for (int q2=0;q2<3;q2++){
        float2 a[8];
        #pragma unroll
        for (int m1=0;m1<8;m1++){
            float2 g = v[m1+8*q2];
            if (q2==0 || m1==0) a[m1]=g;
            else { float2 w=cW24[m1*q2]; if(INV) w.y=-w.y; a[m1]=cmul(g,w); }
        }
        fft8<INV>(a);
        #pragma unroll
        for (int q1=0;q1<8;q1++) out[q2+3*q1]=a[q1];
    }
}

// 24-pt FFT in registers + W384^{n1*k} twiddle + scatter to exchange buffer
template<bool INV>
__device__ __forceinline__ void phaseA(float2 v[24], float2* exrow, int n1,
                                       const float2* __restrict__ tw)
{
    float2 o[24];
    fft24<INV>(v, o);
    #pragma unroll
    for (int k=0;k<24;k++){
        float2 w = tw[n1*k]; if(INV) w.y=-w.y;
        exrow[k*17 + n1] = cmul(o[k], w);
    }
}

// ---------------------------------------------------------------------------
__global__ void k0_tw()
{
    int i = threadIdx.x;
    if (i < Nn) {
        double th = -2.0 * 3.14159265358979323846 * (double)i / (double)Nn;
        g_tw[i] = make_float2((float)cos(th), (float)sin(th));
    }
}

// zero state + build mask/b pack (merged)
__global__ void k0_init(const float* __restrict__ x0, const int* __restrict__ mask)
{
    for (int i = blockIdx.x*blockDim.x + threadIdx.x; i < Bn*NP; i += gridDim.x*blockDim.x) {
        g_x[i] = make_float2(0.f,0.f);
        g_y[i] = make_float2(0.f,0.f);
        g_grad[i] = make_float2(0.f,0.f);
        int b   = i / NP;
        int rem = i - b*NP;
        int w   = rem / Nn;
        int h   = rem - w*Nn;
        int hi  = h*Nn + w;
        float m = (float)mask[b*NP + hi];
        float xr = x0[(size_t)(2*b  )*NP + hi];
        float xi = x0[(size_t)(2*b+1)*NP + hi];
        g_mb[i] = make_float4(m, m*xr, m*xi, 0.f);
    }
}

// interleave csm once: g_csm2[(b*Cn+c)*NP + p] = {re, im}
__global__ void k0_csm(const float* __restrict__ csm)
{
    for (size_t i = (size_t)blockIdx.x*blockDim.x + threadIdx.x;
         i < (size_t)Bn*Cn*NP; i += (size_t)gridDim.x*blockDim.x) {
        size_t p  = i % NP;
        size_t bc = i / NP;
        size_t c  = bc % Cn;
        size_t b  = bc / Cn;
        float re = csm[((b*2+0)*Cn + c)*NP + p];
        float im = csm[((b*2+1)*Cn + c)*NP + p];
        g_csm2[i] = make_float2(re, im);
    }
}

// ---------------------------------------------------------------------------
// K1: fwd FFT over w of coil*y; DIRECT transposed write to g_T1[b,c,kw,h]
// (row-inner mapping in the fft16 phase; no staging pass).
// ---------------------------------------------------------------------------
__global__ void __launch_bounds__(192,5) k1_fwd_rows()
{
    __shared__ float2 tw[Nn];
    __shared__ float2 buf[BUF1];
    const int tid = threadIdx.x;
    for (int i=tid;i<Nn;i+=192) tw[i]=g_tw[i];
    const int blk = blockIdx.x;
    const int h0 = (blk % 48)*R1;
    const int c  = (blk / 48) % Cn;
    const int b  =  blk / (48*Cn);
    __syncthreads();

    if (tid < 16*R1) {
        int row=tid>>4, n1=tid&15;
        int h=h0+row;
        const float2* cp = g_csm2 + ((size_t)(b*Cn+c))*NP + (size_t)h*Nn;
        const float2* yp = g_y + (size_t)b*NP + (size_t)h*Nn;
        float2 v[24];
        #pragma unroll
        for (int n2=0;n2<24;n2++){
            int n = n1+16*n2;
            v[n2] = cmul(ldcs2(cp+n), yp[n]);
        }
        phaseA<false>(v, buf + row*EXRS, n1, tw);
    }
    __syncthreads();
    {
        int row = tid & 7, k2 = tid >> 3;      // row-inner: warp = 8 rows x 4 k2
        float2 hh[16];
        #pragma unroll
        for (int n1=0;n1<16;n1++) hh[n1]=buf[row*EXRS + k2*17 + n1];
        fft16<false>(hh);
        float2* T1 = g_T1 + (size_t)(b*Cn+c)*NP;
        #pragma unroll
        for (int k1=0;k1<16;k1++){
            int k = k2 + 24*k1;
            T1[(size_t)k*Nn + h0 + row] = hh[k1];
        }
    }
}

// ---------------------------------------------------------------------------
// K2: fwd FFT over h, mask & subtract, reverse-network inv FFT over h.
// Reads g_T1[b,c,kw,h] (streaming); DIRECT write g_T2[b,c,h,kw] (scaled).
// ---------------------------------------------------------------------------
__global__ void __launch_bounds__(192,5) k2_cols()
{
    __shared__ float2 tw[Nn];
    __shared__ float2 buf[BUF1];
    const int tid = threadIdx.x;
    for (int i=tid;i<Nn;i+=192) tw[i]=g_tw[i];
    const int blk = blockIdx.x;
    const int w0 = (blk % 48)*R1;
    const int c  = (blk / 48) % Cn;
    const int b  =  blk / (48*Cn);
    __syncthreads();

    // phase 1: load + fwd phaseA (128 threads, n1-inner: coalesced loads)
    const float2* T1 = g_T1 + (size_t)(b*Cn+c)*NP;
    if (tid < 16*R1){
        int rowA=tid>>4, n1=tid&15;
        const float2* src = T1 + (size_t)(w0+rowA)*Nn;
        float2 v[24];
        #pragma unroll
        for (int n2=0;n2<24;n2++) v[n2]=ldcs2(src + n1+16*n2);
        phaseA<false>(v, buf + rowA*EXRS, n1, tw);
    }
    __syncthreads();

    // phase 2: fft16 fwd, mask, fft16 inv (registers), conj twiddle
    const int row=tid/24, k2=tid-row*24;
    float2 hh[16];
    #pragma unroll
    for (int n1=0;n1<16;n1++) hh[n1]=buf[row*EXRS + k2*17 + n1];
    fft16<false>(hh);
    {
        int w = w0+row;
        const float4* mb = g_mb + (size_t)b*NP + (size_t)w*Nn;
        #pragma unroll
        for (int k1=0;k1<16;k1++){
            int k = k2+24*k1;
            float4 q = mb[k];
            hh[k1] = make_float2(q.x*hh[k1].x - q.y, q.x*hh[k1].y - q.z);
        }
    }
    fft16<true>(hh);          // inner inverse over k1; hh now indexed by n1
    __syncthreads();
    #pragma unroll
    for (int n1=0;n1<16;n1++){
        float2 wv = tw[n1*k2]; wv.y = -wv.y;     // W384^{+n1*k2}
        buf[row*EX2RS + n1*25 + k2] = cmul(hh[n1], wv);
    }
    __syncthreads();

    // phase 3: fft24 inverse over k2 (128 threads, row-inner), scale,
    // DIRECT transposed store (no staging).
    if (tid < 16*R1){
        int rowA = tid & 7, n1 = tid >> 3;       // warp = 8 rows x 4 n1
        float2 u[24], xr[24];
        #pragma unroll
        for (int j2=0;j2<24;j2++) u[j2]=buf[rowA*EX2RS + n1*25 + j2];
        fft24<true>(u, xr);
        const float sc = 1.0f/(float)Nn;
        float2* T2 = g_T2 + (size_t)(b*Cn+c)*NP;
        #pragma unroll
        for (int n2=0;n2<24;n2++){
            int n = n1 + 16*n2;
            T2[(size_t)n*Nn + w0 + rowA] = make_float2(xr[n2].x*sc, xr[n2].y*sc);
        }
    }
}

// ---------------------------------------------------------------------------
// K3a: 4 coils per block, R3=4 rows, 96 threads; register accumulation,
// one atomicAdd pair per element per coil-group. grid = Bn*4*96 = 1536.
// ---------------------------------------------------------------------------
__global__ void __launch_bounds__(96) k3a_coils()
{
    __shared__ float2 tw[Nn];
    __shared__ float2 buf[BUF3];
    const int tid = threadIdx.x;
    for (int i=tid;i<Nn;i+=96) tw[i]=g_tw[i];
    const int blk = blockIdx.x;
    const int h0 = (blk % 96)*R3;
    const int cg = (blk / 96) % 4;        // coil group
    const int b  =  blk / (96*4);
    const int row=tid/24, k2=tid-row*24;
    float2 acc[16];
    #pragma unroll
    for (int i=0;i<16;i++) acc[i]=make_float2(0.f,0.f);
    __syncthreads();

    const float sc = 1.0f/(float)Nn;
    #pragma unroll
    for (int cc=0;cc<4;cc++){
        int c = cg*4 + cc;
        if (tid < 16*R3){
            int rowA=tid>>4, n1=tid&15;
            const float2* src = g_T2 + (size_t)(b*Cn+c)*NP + (size_t)(h0+rowA)*Nn;
            float2 v[24];
            #pragma unroll
            for (int n2=0;n2<24;n2++) v[n2]=ldcs2(src + n1+16*n2);
            phaseA<true>(v, buf + rowA*EXRS, n1, tw);
        }
        __syncthreads();
        float2 hh[16];
        #pragma unroll
        for (int n1=0;n1<16;n1++) hh[n1]=buf[row*EXRS + k2*17 + n1];
        fft16<true>(hh);
        const float2* cp = g_csm2 + ((size_t)(b*Cn+c))*NP + (size_t)(h0+row)*Nn;
        #pragma unroll
        for (int k1=0;k1<16;k1++){
            int n = k2+24*k1;
            float2 cv = ldcs2(cp + n); cv.y = -cv.y;   // conj(coil)
            float2 xv = make_float2(hh[k1].x*sc, hh[k1].y*sc);
            float2 p  = cmul(cv, xv);
            acc[k1] = make_float2(acc[k1].x+p.x, acc[k1].y+p.y);
        }
        __syncthreads();
    }
    float* gp = (float*)(g_grad + (size_t)b*NP + (size_t)(h0+row)*Nn);
    #pragma unroll
    for (int k1=0;k1<16;k1++){
        int n = k2+24*k1;
        atomicAdd(gp + 2*n,     acc[k1].x);
        atomicAdd(gp + 2*n + 1, acc[k1].y);
    }
}

// ---------------------------------------------------------------------------
// K3b: pointwise FISTA update + re-zero g_grad for next iteration
// ---------------------------------------------------------------------------
__global__ void __launch_bounds__(256) k3b_fista(const float* __restrict__ zk,
                                                 const float* __restrict__ lam,
                                                 float mu,
                                                 float* __restrict__ out,
                                                 int wout)
{
    int i = blockIdx.x*blockDim.x + threadIdx.x;
    if (i >= Bn*NP) return;
    int b  = i / NP;
    int gi = i - b*NP;
    const float lamv = lam[0];
    float2 grad = g_grad[i];
    g_grad[i] = make_float2(0.f, 0.f);
    float2 yv = g_y[i];
    float2 xo = g_x[i];
    float xnr = yv.x - grad.x;
    float xni = yv.y - grad.y;
    xnr = xnr - lamv*(xnr - zk[(size_t)(b*2+0)*NP + gi]);
    xni = xni - lamv*(xni - zk[(size_t)(b*2+1)*NP + gi]);
    xnr = fmaxf(xnr, 0.f);
    xni = fmaxf(xni, 0.f);
    float ynr = xnr + mu*(xnr - xo.x);
    float yni = xni + mu*(xni - xo.y);
    g_x[i] = make_float2(xnr, xni);
    g_y[i] = make_float2(ynr, yni);
    if (wout) {
        out[(size_t)(b*2+0)*NP + gi] = xnr;
        out[(size_t)(b*2+1)*NP + gi] = xni;
    }
}

// ---------------------------------------------------------------------------
extern "C" void kernel_launch(void* const* d_in, const int* in_sizes, int n_in,
                              void* d_out, int out_size)
{
    const float* z_k = (const float*)d_in[0];
    const float* x0  = (const float*)d_in[1];
    const float* csm = (const float*)d_in[2];
    const float* lam = (const float*)d_in[3];
    const int*   msk = (const int*)  d_in[4];
    float* out = (float*)d_out;

    k0_tw  <<<1, 384>>>();
    k0_init<<<1152, 256>>>(x0, msk);
    k0_csm <<<4608, 256>>>(csm);

    float t = 1.0f;
    const int G12 = Bn*Cn*48;        // 3072
    const int G3a = Bn*4*96;         // 1536
    const int GZ  = (Bn*NP+255)/256; // 2304
    for (int it = 0; it < 20; it++) {
        float tn = (1.0f + sqrtf(1.0f + 4.0f*t*t)) * 0.5f;
        float mu = (t - 1.0f) / tn;
        t = tn;
        k1_fwd_rows<<<G12, 192>>>();
        k2_cols    <<<G12, 192>>>();
        k3a_coils  <<<G3a, 96>>>();
        k3b_fista  <<<GZ, 256>>>(z_k, lam, mu, out, (it == 19) ? 1 : 0);
    }
    (void)in_sizes; (void)n_in; (void)out_size;
}